// round 17
// baseline (speedup 1.0000x reference)
#include <cuda_runtime.h>

// Upscale2d: 2x zero-insert upsample + 4x4 binomial FIR == separable 2-tap
// polyphase: even (a + 3b)/4, odd (3b + c)/4 per axis.
// x: [8,64,256,256] f32 -> y: [8,64,512,512] f32, zero-padded borders.
//
// Terminal point of the small-tile gradient (R13 RPT=4 -> R14 RPT=2 each
// raised DRAM duty via residency): RPT=1. Each tile loads rows r-1, r, r+1
// back-to-back (pure load burst, no loop-carried deps) and emits output
// rows 2r and 2r+1. Cross-tile re-reads are L2 hits (input is L2-resident).
// Shuffle horizontal combines, plain write-back float4 stores.

#define IN_H 256
#define IN_W 256
#define OUT_W 512

__global__ __launch_bounds__(128) void upscale2d_kernel(
    const float* __restrict__ x, float* __restrict__ y)
{
    const int t    = threadIdx.x;              // 0..127: owns cols [2t, 2t+1]
    const int r    = blockIdx.x;               // input row 0..255
    const int p    = blockIdx.y;               // plane (N*C)
    const int lane = threadIdx.x & 31;

    const int c0 = 2 * t;
    const float* xp = x + (size_t)p * IN_H * IN_W;
    float*       yp = y + (size_t)p * OUT_W * OUT_W;

    const bool edgeL = (lane == 0)  && (c0 >= 1);
    const bool edgeR = (lane == 31) && (c0 + 2 < IN_W);

    // raw row load (zero outside [0, IN_H)); e = cross-warp edge element
    auto loadraw = [&](int rr_, float& e) -> float2 {
        e = 0.f;
        if (rr_ < 0 || rr_ >= IN_H) return make_float2(0.f, 0.f);
        const float* row = xp + (size_t)rr_ * IN_W;
        if (edgeL) e = __ldg(row + c0 - 1);
        if (edgeR) e = __ldg(row + c0 + 2);
        return *(const float2*)(row + c0);
    };

    // horizontal pre-combines: H = even phase, O = odd phase (2 columns)
    auto comb = [&](float2 c, float e,
                    float& H0, float& O0, float& H1, float& O1) {
        float l  = __shfl_up_sync(0xffffffffu, c.y, 1);   // col c0-1
        float rr = __shfl_down_sync(0xffffffffu, c.x, 1); // col c0+2
        if (lane == 0)  l  = e;
        if (lane == 31) rr = e;
        H0 = l   + 3.f * c.x;  O0 = 3.f * c.x + c.y;
        H1 = c.x + 3.f * c.y;  O1 = 3.f * c.y + rr;
    };

    // all three loads back-to-back: rows r-1, r, r+1
    float eU, eC, eD;
    float2 rU = loadraw(r - 1, eU);
    float2 rC = loadraw(r,     eC);
    float2 rD = loadraw(r + 1, eD);

    float UH0, UO0, UH1, UO1;
    float CH0, CO0, CH1, CO1;
    float DH0, DO0, DH1, DO1;
    comb(rU, eU, UH0, UO0, UH1, UO1);
    comb(rC, eC, CH0, CO0, CH1, CO1);
    comb(rD, eD, DH0, DO0, DH1, DO1);

    // output row 2r: vertical even phase (up + 3*cur) * 1/16
    {
        float4 v;
        v.x = (UH0 + 3.f * CH0) * 0.0625f;
        v.y = (UO0 + 3.f * CO0) * 0.0625f;
        v.z = (UH1 + 3.f * CH1) * 0.0625f;
        v.w = (UO1 + 3.f * CO1) * 0.0625f;
        *(float4*)(yp + (size_t)(2 * r) * OUT_W + 2 * c0) = v;
    }
    // output row 2r+1: vertical odd phase (3*cur + down) * 1/16
    {
        float4 v;
        v.x = (3.f * CH0 + DH0) * 0.0625f;
        v.y = (3.f * CO0 + DO0) * 0.0625f;
        v.z = (3.f * CH1 + DH1) * 0.0625f;
        v.w = (3.f * CO1 + DO1) * 0.0625f;
        *(float4*)(yp + (size_t)(2 * r + 1) * OUT_W + 2 * c0) = v;
    }
}

extern "C" void kernel_launch(void* const* d_in, const int* in_sizes, int n_in,
                              void* d_out, int out_size)
{
    const float* x = (const float*)d_in[0];
    float* y = (float*)d_out;
    int planes = in_sizes[0] / (IN_H * IN_W);            // 512
    dim3 grid(IN_H, planes);                             // (256, 512)
    upscale2d_kernel<<<grid, 128>>>(x, y);
}